// round 14
// baseline (speedup 1.0000x reference)
#include <cuda_runtime.h>
#include <cstdint>

// QuantumDotProductCircuit:
//   ov(b) = a(b)^T M b(b),  score = |ov|^2, out = (1+score)/2
// a,b are real Kronecker product states from RY(tanh(x)*pi) on |0>,
// M = U_q^dagger U_k is a fixed 16x16 complex matrix built from W_q,W_k.
// Two kernels; PDL collapses the inter-kernel gap (measured gap ~0).
// launch_bounds(256,5) forces the 51-reg budget -> 5 blocks/SM (R1's
// measured-best residency), overriding PDL-induced register inflation.

__device__ ulonglong2 g_M[128];  // 16x16 complex, interleaved (re,im), row-major

__device__ __forceinline__ unsigned long long pk2(float lo, float hi) {
    unsigned long long r;
    asm("mov.b64 %0, {%1, %2};" : "=l"(r) : "f"(lo), "f"(hi));
    return r;
}
__device__ __forceinline__ float2 upk2(unsigned long long v) {
    float2 r;
    asm("mov.b64 {%0, %1}, %2;" : "=f"(r.x), "=f"(r.y) : "l"(v));
    return r;
}
__device__ __forceinline__ unsigned long long fma2(unsigned long long a,
                                                   unsigned long long b,
                                                   unsigned long long c) {
    unsigned long long d;
    asm("fma.rn.f32x2 %0, %1, %2, %3;" : "=l"(d) : "l"(a), "l"(b), "l"(c));
    return d;
}
__device__ __forceinline__ unsigned long long add2(unsigned long long a,
                                                   unsigned long long b) {
    unsigned long long d;
    asm("add.rn.f32x2 %0, %1, %2;" : "=l"(d) : "l"(a), "l"(b));
    return d;
}

// fast tanh: (e^{2x}-1)/(e^{2x}+1), EX2 + RCP.approx. rel err ~1e-6.
__device__ __forceinline__ float fast_tanh(float x) {
    x = fminf(fmaxf(x, -9.0f), 9.0f);
    float e = __expf(2.0f * x);
    return __fdividef(e - 1.0f, e + 1.0f);
}

// ---------------------------------------------------------------------------
// Prep kernel: build U_q, U_k (16x16) by simulating the Rot+CNOT layers on
// each basis state, then M = U_q^dagger U_k. One block, 256 threads.
// Wire w maps to index bit (3-w) (reference reshape puts wire 0 as MSB).
// Triggers programmatic launch completion after M is globally visible.
// ---------------------------------------------------------------------------
__global__ void qdp_prep(const float* __restrict__ Wq, const float* __restrict__ Wk) {
    __shared__ float2 U[2][16][16];  // [matrix][row t][column c]
    int tid = threadIdx.x;

    if (tid < 32) {
        int m = tid >> 4;       // 0 = q, 1 = k
        int c = tid & 15;       // column = input basis state
        const float* W = m ? Wk : Wq;

        float vr[16], vi[16];
#pragma unroll
        for (int s = 0; s < 16; s++) { vr[s] = (s == c) ? 1.0f : 0.0f; vi[s] = 0.0f; }

#pragma unroll
        for (int layer = 0; layer < 2; layer++) {
#pragma unroll
            for (int w = 0; w < 4; w++) {
                float phi = W[layer * 12 + w * 3 + 0];
                float th  = W[layer * 12 + w * 3 + 1];
                float om  = W[layer * 12 + w * 3 + 2];
                float cth, sth; __sincosf(0.5f * th, &sth, &cth);
                float sA, cA, sB, cB;
                __sincosf(0.5f * (phi + om), &sA, &cA);
                __sincosf(0.5f * (phi - om), &sB, &cB);
                float u00r =  cA * cth, u00i = -sA * cth;
                float u01r = -cB * sth, u01i = -sB * sth;
                float u10r =  cB * sth, u10i = -sB * sth;
                float u11r =  cA * cth, u11i =  sA * cth;
                const int st = 8 >> w;
#pragma unroll
                for (int s = 0; s < 16; s++) {
                    if (!(s & st)) {
                        const int s1 = s | st;
                        float xr = vr[s], xi = vi[s], yr = vr[s1], yi = vi[s1];
                        vr[s]  = u00r * xr - u00i * xi + u01r * yr - u01i * yi;
                        vi[s]  = u00r * xi + u00i * xr + u01r * yi + u01i * yr;
                        vr[s1] = u10r * xr - u10i * xi + u11r * yr - u11i * yi;
                        vi[s1] = u10r * xi + u10i * xr + u11r * yi + u11i * yr;
                    }
                }
            }
#pragma unroll
            for (int w = 0; w < 3; w++) {
                const int cm = 8 >> w, tm = 4 >> w;
#pragma unroll
                for (int s = 0; s < 16; s++) {
                    if ((s & cm) && !(s & tm)) {
                        const int s1 = s | tm;
                        float tr = vr[s], ti = vi[s];
                        vr[s] = vr[s1]; vi[s] = vi[s1];
                        vr[s1] = tr;    vi[s1] = ti;
                    }
                }
            }
        }
#pragma unroll
        for (int t = 0; t < 16; t++) U[m][t][c] = make_float2(vr[t], vi[t]);
    }
    __syncthreads();

    // M[i][j] = sum_t conj(Uq[t][i]) * Uk[t][j]
    int i = tid >> 4, j = tid & 15;
    float mr = 0.0f, mi = 0.0f;
#pragma unroll
    for (int t = 0; t < 16; t++) {
        float2 q = U[0][t][i];
        float2 k = U[1][t][j];
        mr += q.x * k.x + q.y * k.y;
        mi += q.x * k.y - q.y * k.x;
    }
    float* gm = (float*)g_M;
    gm[2 * (i * 16 + j) + 0] = mr;
    gm[2 * (i * 16 + j) + 1] = mi;

    // Make M visible, then allow the dependent main kernel to launch.
    __threadfence();
    __syncthreads();
    cudaTriggerProgrammaticLaunchCompletion();
}

// ---------------------------------------------------------------------------
// Main kernel: R1 structure (one thread/element, 256-thr blocks).
// launch_bounds(256, 5) pins the register budget at 51 (R1's body compiles
// at 48) -> 5 blocks/SM, occ ~50% — the measured-best configuration.
// ---------------------------------------------------------------------------
__global__ void __launch_bounds__(256, 5) qdp_main(
        const float4* __restrict__ q4, const float4* __restrict__ k4,
        float* __restrict__ out, int B) {
    // Wait for prep's g_M before anything else (PDL dependency).
    cudaGridDependencySynchronize();
    asm volatile("" ::: "memory");   // discourage LDG hoisting above the sync

    __shared__ ulonglong2 Msh[128];
    int tid = threadIdx.x;
    if (tid < 128) Msh[tid] = g_M[tid];
    __syncthreads();

    int idx = blockIdx.x * 256 + tid;
    if (idx >= B) idx = B - 1;

    // rows are 64 floats = 16 float4; we need float4 #0 of each row
    float4 qv = q4[(size_t)idx * 16];
    float4 kv = k4[(size_t)idx * 16];

    const float HP = 1.5707963267948966f;  // pi/2 (half-angle scale)
    float cs[4], sn[4];
    __sincosf(fast_tanh(qv.x) * HP, &sn[0], &cs[0]);
    __sincosf(fast_tanh(qv.y) * HP, &sn[1], &cs[1]);
    __sincosf(fast_tanh(qv.z) * HP, &sn[2], &cs[2]);
    __sincosf(fast_tanh(qv.w) * HP, &sn[3], &cs[3]);
    float a01[4] = {cs[0]*cs[1], cs[0]*sn[1], sn[0]*cs[1], sn[0]*sn[1]};
    float a23[4] = {cs[2]*cs[3], cs[2]*sn[3], sn[2]*cs[3], sn[2]*sn[3]};

    __sincosf(fast_tanh(kv.x) * HP, &sn[0], &cs[0]);
    __sincosf(fast_tanh(kv.y) * HP, &sn[1], &cs[1]);
    __sincosf(fast_tanh(kv.z) * HP, &sn[2], &cs[2]);
    __sincosf(fast_tanh(kv.w) * HP, &sn[3], &cs[3]);
    float b01[4] = {cs[0]*cs[1], cs[0]*sn[1], sn[0]*cs[1], sn[0]*sn[1]};
    float b23[4] = {cs[2]*cs[3], cs[2]*sn[3], sn[2]*cs[3], sn[2]*sn[3]};

    unsigned long long bp[16];
#pragma unroll
    for (int j = 0; j < 16; j++) {
        float v = b01[j >> 2] * b23[j & 3];
        bp[j] = pk2(v, v);
    }

    // ov = sum_i av[i] * (sum_j M[i][j] * b[j]), packed (re,im) lanes
    unsigned long long ov0 = 0ULL, ov1 = 0ULL;
#pragma unroll
    for (int i = 0; i < 16; i++) {
        unsigned long long t0 = 0ULL, t1 = 0ULL;
#pragma unroll
        for (int jj = 0; jj < 8; jj++) {
            ulonglong2 m = Msh[i * 8 + jj];     // two complex entries
            t0 = fma2(m.x, bp[2 * jj + 0], t0);
            t1 = fma2(m.y, bp[2 * jj + 1], t1);
        }
        float avi = a01[i >> 2] * a23[i & 3];
        unsigned long long avp = pk2(avi, avi);
        unsigned long long s = add2(t0, t1);
        if (i & 1) ov1 = fma2(avp, s, ov1);
        else       ov0 = fma2(avp, s, ov0);
    }
    float2 o = upk2(add2(ov0, ov1));
    float score = o.x * o.x + o.y * o.y;
    out[idx] = fmaf(0.5f, score, 0.5f);
}

extern "C" void kernel_launch(void* const* d_in, const int* in_sizes, int n_in,
                              void* d_out, int out_size) {
    const float* q  = (const float*)d_in[0];
    const float* k  = (const float*)d_in[1];
    const float* Wq = (const float*)d_in[2];
    const float* Wk = (const float*)d_in[3];
    int B = in_sizes[0] / 64;
    int nblk = (B + 255) / 256;

    qdp_prep<<<1, 256>>>(Wq, Wk);

    // PDL launch: main's blocks spin up while prep finishes; dependency is
    // released by prep's cudaTriggerProgrammaticLaunchCompletion().
    cudaLaunchConfig_t cfg = {};
    cfg.gridDim  = dim3((unsigned)nblk, 1, 1);
    cfg.blockDim = dim3(256, 1, 1);
    cudaLaunchAttribute attrs[1];
    attrs[0].id = cudaLaunchAttributeProgrammaticStreamSerialization;
    attrs[0].val.programmaticStreamSerializationAllowed = 1;
    cfg.attrs = attrs;
    cfg.numAttrs = 1;

    cudaError_t err = cudaLaunchKernelEx(&cfg, qdp_main,
                                         (const float4*)q, (const float4*)k,
                                         (float*)d_out, B);
    if (err != cudaSuccess) {
        qdp_main<<<nblk, 256>>>((const float4*)q, (const float4*)k,
                                (float*)d_out, B);
    }
}